// round 11
// baseline (speedup 1.0000x reference)
#include <cuda_runtime.h>
#include <cstdint>
#include <math.h>

#define N_NODES 10000
#define E_EDGES 640000
#define DIM     128
#define HEADS   4

// device globals zero-init at load; consumers re-zero what they read.
__device__ float g_M[128 * 512];         // M[c][h*128+k], scale folded
__device__ float g_B[512];               // B[h*128+k], scale folded
__device__ float g_Mb[128 * 4];          // Mb[c][h], scale folded
__device__ float g_cb[4];                // scale folded
__device__ float g_wt[N_NODES * 512];    // w-tilde [n][h*128+k]
__device__ float g_c[N_NODES * HEADS];
__device__ float g_S[N_NODES * 512];     // self-cleaned by k_vproj
__device__ float g_agg[N_NODES * DIM];
__device__ float g_den[N_NODES * HEADS]; // self-cleaned by k_vproj
__device__ int   g_cnt[N_NODES];         // self-cleaned by k_scan
__device__ int   g_cur[N_NODES];         // fully rewritten by k_scan
__device__ int   g_perm[E_EDGES];        // fully rewritten by scatter

__device__ __forceinline__ int detect32(const void* ei) {
    const long long* p = (const long long*)ei;
    long long x = 0;
    #pragma unroll
    for (int i = 0; i < 8; i++) x |= p[i];
    return (((unsigned long long)x) >> 32) != 0ull;
}
__device__ __forceinline__ int dst_at(const void* ei, int e, int is32) {
    return is32 ? ((const int*)ei)[e] : (int)((const long long*)ei)[e];
}

// ---------------- launch 0: prep (blocks [0,32)) + hist (rest); NO smem ----------------
__global__ __launch_bounds__(256) void k_hist_prep(const float* __restrict__ Wq,
                                                   const float* __restrict__ bq,
                                                   const float* __restrict__ Wk,
                                                   const float* __restrict__ bk,
                                                   const void* __restrict__ ei, int E) {
    const float scale = 0.17677669529663689f;  // 1/sqrt(32)
    int tid = threadIdx.x;
    if ((int)blockIdx.x >= 32) {
        __shared__ int s32;
        if (tid == 0) s32 = detect32(ei);
        __syncthreads();
        int e = (blockIdx.x - 32) * blockDim.x + tid;
        if (e < E) atomicAdd(&g_cnt[dst_at(ei, e, s32)], 1);
        return;
    }
    int b = blockIdx.x;
    int c = tid & 127, kp = tid >> 7;
    #pragma unroll
    for (int h = 0; h < 4; h++) {
        float wq[32];
        #pragma unroll
        for (int d4 = 0; d4 < 8; d4++) {
            float4 v = __ldg((const float4*)&Wq[c * 128 + h * 32 + d4 * 4]);
            wq[d4 * 4 + 0] = v.x; wq[d4 * 4 + 1] = v.y;
            wq[d4 * 4 + 2] = v.z; wq[d4 * 4 + 3] = v.w;
        }
        #pragma unroll
        for (int j = 0; j < 2; j++) {
            int kl = 2 * kp + j;
            float s = 0.f;
            #pragma unroll
            for (int d = 0; d < 32; d++)
                s += wq[d] * __ldg(&Wk[(b * 4 + kl) * 128 + h * 32 + d]);
            g_M[c * 512 + h * 128 + b * 4 + kl] = s * scale;
        }
    }
    if (tid < 16) {
        int kl = tid >> 2, h = tid & 3;
        float s = 0.f;
        #pragma unroll
        for (int d = 0; d < 32; d++)
            s += __ldg(&bq[h * 32 + d]) * __ldg(&Wk[(b * 4 + kl) * 128 + h * 32 + d]);
        g_B[h * 128 + b * 4 + kl] = s * scale;
    }
    if (b == 0) {
        int hp = tid >> 7;
        #pragma unroll
        for (int j = 0; j < 2; j++) {
            int h = 2 * hp + j;
            float s = 0.f;
            #pragma unroll
            for (int d = 0; d < 32; d++)
                s += __ldg(&Wq[c * 128 + h * 32 + d]) * __ldg(&bk[h * 32 + d]);
            g_Mb[c * 4 + h] = s * scale;
        }
        if (tid < 4) {
            float s = 0.f;
            #pragma unroll
            for (int d = 0; d < 32; d++) s += __ldg(&bq[tid * 32 + d]) * __ldg(&bk[tid * 32 + d]);
            g_cb[tid] = s * scale;
        }
    }
}

// ---------------- launch 1: scan (+ self-clean g_cnt) ----------------
__global__ __launch_bounds__(1024) void k_scan(int n) {
    __shared__ int ws[32];
    int t = threadIdx.x, lane = t & 31, wd = t >> 5;
    int per = (n + 1023) / 1024;
    int base = t * per;
    int s = 0;
    for (int i = 0; i < per; i++) {
        int idx = base + i;
        if (idx < n) s += g_cnt[idx];
    }
    int incl = s;
    #pragma unroll
    for (int off = 1; off < 32; off <<= 1) {
        int y = __shfl_up_sync(0xffffffffu, incl, off);
        if (lane >= off) incl += y;
    }
    if (lane == 31) ws[wd] = incl;
    __syncthreads();
    if (wd == 0) {
        int v = ws[lane];
        int iv = v;
        #pragma unroll
        for (int off = 1; off < 32; off <<= 1) {
            int y = __shfl_up_sync(0xffffffffu, iv, off);
            if (lane >= off) iv += y;
        }
        ws[lane] = iv - v;
    }
    __syncthreads();
    int run = ws[wd] + incl - s;
    for (int i = 0; i < per; i++) {
        int idx = base + i;
        if (idx < n) {
            int v = g_cnt[idx];
            g_cur[idx] = run;
            run += v;
            g_cnt[idx] = 0;
        }
    }
}

// ---------------- launch 2: k_wt (smem = As only) + scatter ----------------
__global__ __launch_bounds__(256) void k_wt_scatter(const float* __restrict__ X,
                                                    const void* __restrict__ ei,
                                                    int n, int E, int wtBlocks) {
    if ((int)blockIdx.x >= wtBlocks) {
        __shared__ int s32;
        if (threadIdx.x == 0) s32 = detect32(ei);
        __syncthreads();
        int e = (blockIdx.x - wtBlocks) * blockDim.x + threadIdx.x;
        if (e < E) {
            int pos = atomicAdd(&g_cur[dst_at(ei, e, s32)], 1);
            g_perm[pos] = e;
        }
        return;
    }
    extern __shared__ float sv[];
    float* As = sv;               // [64][132]
    int tid = threadIdx.x;
    int b = blockIdx.x;
    int row0 = (b >> 2) * 64;
    int by = b & 3;

    for (int i = tid; i < 64 * DIM; i += 256) {
        int r = i >> 7, c = i & 127;
        int gr = row0 + r;
        As[r * 132 + c] = (gr < n) ? X[gr * DIM + c] : 0.f;
    }
    __syncthreads();

    int cg = (tid & 31) * 4, rg = (tid >> 5) * 8;
    float acc[8][4] = {};
    #pragma unroll 4
    for (int d = 0; d < DIM; d++) {
        float4 w = __ldg((const float4*)&g_M[d * 512 + by * 128 + cg]);
        #pragma unroll
        for (int rr = 0; rr < 8; rr++) {
            float a = As[(rg + rr) * 132 + d];
            acc[rr][0] += a * w.x; acc[rr][1] += a * w.y;
            acc[rr][2] += a * w.z; acc[rr][3] += a * w.w;
        }
    }
    float4 bb = __ldg((const float4*)&g_B[by * 128 + cg]);
    #pragma unroll
    for (int rr = 0; rr < 8; rr++) {
        int gr = row0 + rg + rr;
        if (gr < n) {
            float4 o = make_float4(acc[rr][0] + bb.x, acc[rr][1] + bb.y,
                                   acc[rr][2] + bb.z, acc[rr][3] + bb.w);
            *(float4*)&g_wt[(size_t)gr * 512 + by * 128 + cg] = o;
        }
    }
    if (by == 0) {
        int nl = tid >> 2, h = tid & 3;
        int node = row0 + nl;
        float s = 0.f;
        #pragma unroll 8
        for (int c = 0; c < 128; c++) s += As[nl * 132 + c] * __ldg(&g_Mb[c * 4 + h]);
        if (node < n) g_c[node * 4 + h] = s + g_cb[h];
    }
}

// ---------------- launch 3 (PROFILED): k_edge — fused score+aggr, head-group mapping ----------------
// Lane l: g = l>>3 (head), s = l&7 (16-element slice). Warp handles 64 perm-
// contiguous edges. acc[j] accumulates head g, elements s*16+j of weighted v.
__global__ __launch_bounds__(256, 3) void k_edge(const float* __restrict__ ke,
                                                 const float* __restrict__ ve,
                                                 const void* __restrict__ ei, int E) {
    __shared__ int s32s;
    if (threadIdx.x == 0) s32s = detect32(ei);
    __syncthreads();
    int is32 = s32s;
    int lane = threadIdx.x & 31;
    int g = lane >> 3, s = lane & 7;
    int gw = (blockIdx.x * blockDim.x + threadIdx.x) >> 5;
    int base = gw * 64;
    if (base >= E) return;
    int cnt = min(64, E - base);

    int pe_l[2], d_l[2];
    #pragma unroll
    for (int j = 0; j < 2; j++) {
        int idx = base + j * 32 + lane;
        if (idx < E) {
            pe_l[j] = g_perm[idx];
            d_l[j] = dst_at(ei, pe_l[j], is32);
        } else { pe_l[j] = 0; d_l[j] = -1; }
    }

    float4 wt0, wt1, wt2, wt3;            // wt[d] slice for (g, s)
    wt0 = wt1 = wt2 = wt3 = make_float4(0.f, 0.f, 0.f, 0.f);
    float c_g = 0.f;
    float4 a0 = make_float4(0.f, 0.f, 0.f, 0.f), a1 = a0, a2 = a0, a3 = a0;
    float aden = 0.f;
    int prevd = -1;

    for (int i = 0; i < cnt; i++) {
        int pe = __shfl_sync(0xffffffffu, pe_l[i >> 5], i & 31);
        int d  = __shfl_sync(0xffffffffu, d_l[i >> 5], i & 31);

        const float4* kr = (const float4*)(ke + (size_t)pe * DIM) + s * 4;
        const float4* vr = (const float4*)(ve + (size_t)pe * DIM) + s * 4;
        float4 k0 = __ldg(kr + 0), k1 = __ldg(kr + 1), k2 = __ldg(kr + 2), k3 = __ldg(kr + 3);
        float4 v0 = __ldg(vr + 0), v1 = __ldg(vr + 1), v2 = __ldg(vr + 2), v3 = __ldg(vr + 3);

        if (d != prevd) {
            if (prevd >= 0) {
                // flush segment: lane writes its 16-element slice of head g
                float* S = g_S + (size_t)prevd * 512 + g * 128 + s * 16;
                atomicAdd(S + 0,  a0.x); atomicAdd(S + 1,  a0.y); atomicAdd(S + 2,  a0.z); atomicAdd(S + 3,  a0.w);
                atomicAdd(S + 4,  a1.x); atomicAdd(S + 5,  a1.y); atomicAdd(S + 6,  a1.z); atomicAdd(S + 7,  a1.w);
                atomicAdd(S + 8,  a2.x); atomicAdd(S + 9,  a2.y); atomicAdd(S + 10, a2.z); atomicAdd(S + 11, a2.w);
                atomicAdd(S + 12, a3.x); atomicAdd(S + 13, a3.y); atomicAdd(S + 14, a3.z); atomicAdd(S + 15, a3.w);
                if (s == 0) atomicAdd(&g_den[prevd * 4 + g], aden);
                a0 = a1 = a2 = a3 = make_float4(0.f, 0.f, 0.f, 0.f);
                aden = 0.f;
            }
            const float4* bw = (const float4*)(g_wt + (size_t)d * 512 + g * 128) + s * 4;
            wt0 = __ldg(bw + 0); wt1 = __ldg(bw + 1); wt2 = __ldg(bw + 2); wt3 = __ldg(bw + 3);
            c_g = __ldg(&g_c[d * 4 + g]);
            prevd = d;
        }

        float q = k0.x * wt0.x + k0.y * wt0.y + k0.z * wt0.z + k0.w * wt0.w
                + k1.x * wt1.x + k1.y * wt1.y + k1.z * wt1.z + k1.w * wt1.w
                + k2.x * wt2.x + k2.y * wt2.y + k2.z * wt2.z + k2.w * wt2.w
                + k3.x * wt3.x + k3.y * wt3.y + k3.z * wt3.z + k3.w * wt3.w;
        q += __shfl_xor_sync(0xffffffffu, q, 1);
        q += __shfl_xor_sync(0xffffffffu, q, 2);
        q += __shfl_xor_sync(0xffffffffu, q, 4);
        float e = __expf(q + c_g);

        a0.x += e * v0.x; a0.y += e * v0.y; a0.z += e * v0.z; a0.w += e * v0.w;
        a1.x += e * v1.x; a1.y += e * v1.y; a1.z += e * v1.z; a1.w += e * v1.w;
        a2.x += e * v2.x; a2.y += e * v2.y; a2.z += e * v2.z; a2.w += e * v2.w;
        a3.x += e * v3.x; a3.y += e * v3.y; a3.z += e * v3.z; a3.w += e * v3.w;
        aden += e;
    }
    // final flush
    {
        float* S = g_S + (size_t)prevd * 512 + g * 128 + s * 16;
        atomicAdd(S + 0,  a0.x); atomicAdd(S + 1,  a0.y); atomicAdd(S + 2,  a0.z); atomicAdd(S + 3,  a0.w);
        atomicAdd(S + 4,  a1.x); atomicAdd(S + 5,  a1.y); atomicAdd(S + 6,  a1.z); atomicAdd(S + 7,  a1.w);
        atomicAdd(S + 8,  a2.x); atomicAdd(S + 9,  a2.y); atomicAdd(S + 10, a2.z); atomicAdd(S + 11, a2.w);
        atomicAdd(S + 12, a3.x); atomicAdd(S + 13, a3.y); atomicAdd(S + 14, a3.z); atomicAdd(S + 15, a3.w);
        if (s == 0) atomicAdd(&g_den[prevd * 4 + g], aden);
    }
}

// ---------------- launch 4: agg = (S @ Wv)/den + bv (+ self-clean; smem = Ss only) ----------------
__global__ __launch_bounds__(256) void k_vproj(const float* __restrict__ Wv,
                                               const float* __restrict__ bv, int n) {
    extern __shared__ float sq[];
    float* Ss = sq;               // [32][4][136]
    int tid = threadIdx.x;
    int row0 = blockIdx.x * 32;
    for (int i = tid; i < 32 * 512; i += 256) {
        int nl = i >> 9, rest = i & 511;
        int h = rest >> 7, d = rest & 127;
        int gr = row0 + nl;
        float v = 0.f;
        if (gr < n) {
            size_t idx = (size_t)gr * 512 + rest;
            v = g_S[idx];
            g_S[idx] = 0.f;
        }
        Ss[nl * 544 + h * 136 + d] = v;
    }
    __syncthreads();
    int cg = (tid & 31) * 4, rg = (tid >> 5) * 4;
    int h = cg >> 5;
    float acc[4][4] = {};
    #pragma unroll 8
    for (int d = 0; d < DIM; d++) {
        float4 wv = __ldg((const float4*)&Wv[d * DIM + cg]);
        float a0 = Ss[(rg + 0) * 544 + h * 136 + d];
        float a1 = Ss[(rg + 1) * 544 + h * 136 + d];
        float a2 = Ss[(rg + 2) * 544 + h * 136 + d];
        float a3 = Ss[(rg + 3) * 544 + h * 136 + d];
        acc[0][0] += a0 * wv.x; acc[0][1] += a0 * wv.y; acc[0][2] += a0 * wv.z; acc[0][3] += a0 * wv.w;
        acc[1][0] += a1 * wv.x; acc[1][1] += a1 * wv.y; acc[1][2] += a1 * wv.z; acc[1][3] += a1 * wv.w;
        acc[2][0] += a2 * wv.x; acc[2][1] += a2 * wv.y; acc[2][2] += a2 * wv.z; acc[2][3] += a2 * wv.w;
        acc[3][0] += a3 * wv.x; acc[3][1] += a3 * wv.y; acc[3][2] += a3 * wv.z; acc[3][3] += a3 * wv.w;
    }
    float4 bb = __ldg((const float4*)&bv[cg]);
    #pragma unroll
    for (int rr = 0; rr < 4; rr++) {
        int gr = row0 + rg + rr;
        if (gr < n) {
            float den = g_den[gr * HEADS + h];
            float4 o;
            if (den > 0.f) {
                float inv = 1.f / den;
                o = make_float4(acc[rr][0] * inv + bb.x, acc[rr][1] * inv + bb.y,
                                acc[rr][2] * inv + bb.z, acc[rr][3] * inv + bb.w);
            } else {
                o = make_float4(0.f, 0.f, 0.f, 0.f);
            }
            *(float4*)&g_agg[gr * DIM + cg] = o;
        }
    }
    __syncthreads();
    for (int i = tid; i < 32 * HEADS; i += 256) {
        int gr = row0 + (i >> 2);
        if (gr < n) g_den[gr * HEADS + (i & 3)] = 0.f;
    }
}

// ---------------- launch 5: out = agg @ Wo + bo (smem = As only) ----------------
__global__ __launch_bounds__(256) void k_out(const float* __restrict__ W,
                                             const float* __restrict__ b,
                                             float* __restrict__ Y, int n) {
    extern __shared__ float so[];
    float* As = so;               // [32][132]
    int tid = threadIdx.x;
    int row0 = blockIdx.x * 32;
    for (int i = tid; i < 32 * DIM; i += 256) {
        int r = i >> 7, c = i & 127;
        int gr = row0 + r;
        As[r * 132 + c] = (gr < n) ? g_agg[gr * DIM + c] : 0.f;
    }
    __syncthreads();
    int cg = (tid & 31) * 4, rg = (tid >> 5) * 4;
    float acc[4][4] = {};
    #pragma unroll 8
    for (int d = 0; d < DIM; d++) {
        float4 w = __ldg((const float4*)&W[d * DIM + cg]);
        float a0 = As[(rg + 0) * 132 + d];
        float a1 = As[(rg + 1) * 132 + d];
        float a2 = As[(rg + 2) * 132 + d];
        float a3 = As[(rg + 3) * 132 + d];
        acc[0][0] += a0 * w.x; acc[0][1] += a0 * w.y; acc[0][2] += a0 * w.z; acc[0][3] += a0 * w.w;
        acc[1][0] += a1 * w.x; acc[1][1] += a1 * w.y; acc[1][2] += a1 * w.z; acc[1][3] += a1 * w.w;
        acc[2][0] += a2 * w.x; acc[2][1] += a2 * w.y; acc[2][2] += a2 * w.z; acc[2][3] += a2 * w.w;
        acc[3][0] += a3 * w.x; acc[3][1] += a3 * w.y; acc[3][2] += a3 * w.z; acc[3][3] += a3 * w.w;
    }
    float4 bb = __ldg((const float4*)&b[cg]);
    #pragma unroll
    for (int rr = 0; rr < 4; rr++) {
        int gr = row0 + rg + rr;
        if (gr < n) {
            float4 o = make_float4(acc[rr][0] + bb.x, acc[rr][1] + bb.y,
                                   acc[rr][2] + bb.z, acc[rr][3] + bb.w);
            *(float4*)&Y[gr * DIM + cg] = o;
        }
    }
}

extern "C" void kernel_launch(void* const* d_in, const int* in_sizes, int n_in,
                              void* d_out, int out_size) {
    const float* q_nodes = (const float*)d_in[0];
    const float* k_edges = (const float*)d_in[1];
    const float* v_edges = (const float*)d_in[2];
    const float* Wq = (const float*)d_in[3];
    const float* bq = (const float*)d_in[4];
    const float* Wk = (const float*)d_in[5];
    const float* bk = (const float*)d_in[6];
    const float* Wv = (const float*)d_in[7];
    const float* bv = (const float*)d_in[8];
    const float* Wo = (const float*)d_in[9];
    const float* bo = (const float*)d_in[10];
    const void*  ei = (const void*)d_in[11];

    int N = in_sizes[0] / DIM;
    int E = in_sizes[1] / DIM;

    const int smem_ws  = 64 * 132 * (int)sizeof(float);   // 33792
    const int smem_vp  = 32 * 544 * (int)sizeof(float);   // 69632
    const int smem_out = 32 * 132 * (int)sizeof(float);   // 16896
    cudaFuncSetAttribute(k_wt_scatter, cudaFuncAttributeMaxDynamicSharedMemorySize, smem_ws);
    cudaFuncSetAttribute(k_vproj, cudaFuncAttributeMaxDynamicSharedMemorySize, smem_vp);
    cudaFuncSetAttribute(k_out, cudaFuncAttributeMaxDynamicSharedMemorySize, smem_out);

    int nblk = (N + 31) / 32;
    int histBlocks = (E + 255) / 256;
    int wtBlocks = ((N + 63) / 64) * 4;
    int ewarps = (E + 63) / 64;
    int eblocks = (ewarps + 7) / 8;

    k_hist_prep<<<32 + histBlocks, 256>>>(Wq, bq, Wk, bk, ei, E);                        // 0
    k_scan<<<1, 1024>>>(N);                                                              // 1
    k_wt_scatter<<<wtBlocks + histBlocks, 256, smem_ws>>>(q_nodes, ei, N, E, wtBlocks);  // 2
    k_edge<<<eblocks, 256>>>(k_edges, v_edges, ei, E);                                   // 3 (profiled)
    k_vproj<<<nblk, 256, smem_vp>>>(Wv, bv, N);                                          // 4
    k_out<<<nblk, 256, smem_out>>>(Wo, bo, (float*)d_out, N);                            // 5
}

// round 12
// speedup vs baseline: 1.2321x; 1.2321x over previous
#include <cuda_runtime.h>
#include <cstdint>
#include <math.h>

#define N_NODES 10000
#define E_EDGES 640000
#define DIM     128
#define HEADS   4

// device globals zero-init at load; consumers re-zero what they read.
__device__ float g_M[128 * 512];         // M[c][h*128+k], scale folded
__device__ float g_B[512];               // B[h*128+k], scale folded
__device__ float g_Mb[128 * 4];          // Mb[c][h], scale folded
__device__ float g_cb[4];                // scale folded
__device__ float g_wt[N_NODES * 512];    // w-tilde [n][h*128+k]
__device__ float g_c[N_NODES * HEADS];
__device__ float g_S[N_NODES * 512];     // self-cleaned by k_vproj
__device__ float g_agg[N_NODES * DIM];
__device__ float g_den[N_NODES * HEADS]; // self-cleaned by k_vproj
__device__ int   g_cnt[N_NODES];         // self-cleaned by k_scan
__device__ int   g_cur[N_NODES];         // fully rewritten by k_scan
__device__ int   g_perm[E_EDGES];        // fully rewritten by scatter

__device__ __forceinline__ int detect32(const void* ei) {
    const long long* p = (const long long*)ei;
    long long x = 0;
    #pragma unroll
    for (int i = 0; i < 8; i++) x |= p[i];
    return (((unsigned long long)x) >> 32) != 0ull;
}
__device__ __forceinline__ int dst_at(const void* ei, int e, int is32) {
    return is32 ? ((const int*)ei)[e] : (int)((const long long*)ei)[e];
}

// ---------------- launch 0: prep (blocks [0,32)) + hist (rest); NO smem ----------------
__global__ __launch_bounds__(256) void k_hist_prep(const float* __restrict__ Wq,
                                                   const float* __restrict__ bq,
                                                   const float* __restrict__ Wk,
                                                   const float* __restrict__ bk,
                                                   const void* __restrict__ ei, int E) {
    const float scale = 0.17677669529663689f;  // 1/sqrt(32)
    int tid = threadIdx.x;
    if ((int)blockIdx.x >= 32) {
        __shared__ int s32;
        if (tid == 0) s32 = detect32(ei);
        __syncthreads();
        int e = (blockIdx.x - 32) * blockDim.x + tid;
        if (e < E) atomicAdd(&g_cnt[dst_at(ei, e, s32)], 1);
        return;
    }
    int b = blockIdx.x;
    int c = tid & 127, kp = tid >> 7;
    #pragma unroll
    for (int h = 0; h < 4; h++) {
        float wq[32];
        #pragma unroll
        for (int d4 = 0; d4 < 8; d4++) {
            float4 v = __ldg((const float4*)&Wq[c * 128 + h * 32 + d4 * 4]);
            wq[d4 * 4 + 0] = v.x; wq[d4 * 4 + 1] = v.y;
            wq[d4 * 4 + 2] = v.z; wq[d4 * 4 + 3] = v.w;
        }
        #pragma unroll
        for (int j = 0; j < 2; j++) {
            int kl = 2 * kp + j;
            float s = 0.f;
            #pragma unroll
            for (int d = 0; d < 32; d++)
                s += wq[d] * __ldg(&Wk[(b * 4 + kl) * 128 + h * 32 + d]);
            g_M[c * 512 + h * 128 + b * 4 + kl] = s * scale;
        }
    }
    if (tid < 16) {
        int kl = tid >> 2, h = tid & 3;
        float s = 0.f;
        #pragma unroll
        for (int d = 0; d < 32; d++)
            s += __ldg(&bq[h * 32 + d]) * __ldg(&Wk[(b * 4 + kl) * 128 + h * 32 + d]);
        g_B[h * 128 + b * 4 + kl] = s * scale;
    }
    if (b == 0) {
        int hp = tid >> 7;
        #pragma unroll
        for (int j = 0; j < 2; j++) {
            int h = 2 * hp + j;
            float s = 0.f;
            #pragma unroll
            for (int d = 0; d < 32; d++)
                s += __ldg(&Wq[c * 128 + h * 32 + d]) * __ldg(&bk[h * 32 + d]);
            g_Mb[c * 4 + h] = s * scale;
        }
        if (tid < 4) {
            float s = 0.f;
            #pragma unroll
            for (int d = 0; d < 32; d++) s += __ldg(&bq[tid * 32 + d]) * __ldg(&bk[tid * 32 + d]);
            g_cb[tid] = s * scale;
        }
    }
}

// ---------------- launch 1: scan (+ self-clean g_cnt) ----------------
__global__ __launch_bounds__(1024) void k_scan(int n) {
    __shared__ int ws[32];
    int t = threadIdx.x, lane = t & 31, wd = t >> 5;
    int per = (n + 1023) / 1024;
    int base = t * per;
    int s = 0;
    for (int i = 0; i < per; i++) {
        int idx = base + i;
        if (idx < n) s += g_cnt[idx];
    }
    int incl = s;
    #pragma unroll
    for (int off = 1; off < 32; off <<= 1) {
        int y = __shfl_up_sync(0xffffffffu, incl, off);
        if (lane >= off) incl += y;
    }
    if (lane == 31) ws[wd] = incl;
    __syncthreads();
    if (wd == 0) {
        int v = ws[lane];
        int iv = v;
        #pragma unroll
        for (int off = 1; off < 32; off <<= 1) {
            int y = __shfl_up_sync(0xffffffffu, iv, off);
            if (lane >= off) iv += y;
        }
        ws[lane] = iv - v;
    }
    __syncthreads();
    int run = ws[wd] + incl - s;
    for (int i = 0; i < per; i++) {
        int idx = base + i;
        if (idx < n) {
            int v = g_cnt[idx];
            g_cur[idx] = run;
            run += v;
            g_cnt[idx] = 0;
        }
    }
}

// ---------------- launch 2: k_wt (smem = As only) + scatter ----------------
__global__ __launch_bounds__(256) void k_wt_scatter(const float* __restrict__ X,
                                                    const void* __restrict__ ei,
                                                    int n, int E, int wtBlocks) {
    if ((int)blockIdx.x >= wtBlocks) {
        __shared__ int s32;
        if (threadIdx.x == 0) s32 = detect32(ei);
        __syncthreads();
        int e = (blockIdx.x - wtBlocks) * blockDim.x + threadIdx.x;
        if (e < E) {
            int pos = atomicAdd(&g_cur[dst_at(ei, e, s32)], 1);
            g_perm[pos] = e;
        }
        return;
    }
    extern __shared__ float sv[];
    float* As = sv;               // [64][132]
    int tid = threadIdx.x;
    int b = blockIdx.x;
    int row0 = (b >> 2) * 64;
    int by = b & 3;

    for (int i = tid; i < 64 * DIM; i += 256) {
        int r = i >> 7, c = i & 127;
        int gr = row0 + r;
        As[r * 132 + c] = (gr < n) ? X[gr * DIM + c] : 0.f;
    }
    __syncthreads();

    int cg = (tid & 31) * 4, rg = (tid >> 5) * 8;
    float acc[8][4] = {};
    #pragma unroll 4
    for (int d = 0; d < DIM; d++) {
        float4 w = __ldg((const float4*)&g_M[d * 512 + by * 128 + cg]);
        #pragma unroll
        for (int rr = 0; rr < 8; rr++) {
            float a = As[(rg + rr) * 132 + d];
            acc[rr][0] += a * w.x; acc[rr][1] += a * w.y;
            acc[rr][2] += a * w.z; acc[rr][3] += a * w.w;
        }
    }
    float4 bb = __ldg((const float4*)&g_B[by * 128 + cg]);
    #pragma unroll
    for (int rr = 0; rr < 8; rr++) {
        int gr = row0 + rg + rr;
        if (gr < n) {
            float4 o = make_float4(acc[rr][0] + bb.x, acc[rr][1] + bb.y,
                                   acc[rr][2] + bb.z, acc[rr][3] + bb.w);
            *(float4*)&g_wt[(size_t)gr * 512 + by * 128 + cg] = o;
        }
    }
    if (by == 0) {
        int nl = tid >> 2, h = tid & 3;
        int node = row0 + nl;
        float s = 0.f;
        #pragma unroll 8
        for (int c = 0; c < 128; c++) s += As[nl * 132 + c] * __ldg(&g_Mb[c * 4 + h]);
        if (node < n) g_c[node * 4 + h] = s + g_cb[h];
    }
}

// ---------------- launch 3 (PROFILED): k_edge — fused, coalesced, 9-shfl reduce ----------------
// Lane owns bytes [lane*16, lane*16+16) of each 512B row (1 LDG.128 per row).
// Warp handles 64 perm-contiguous edges, depth-2 prefetch.
__global__ __launch_bounds__(256, 3) void k_edge(const float* __restrict__ ke,
                                                 const float* __restrict__ ve,
                                                 const void* __restrict__ ei, int E) {
    __shared__ int s32s;
    if (threadIdx.x == 0) s32s = detect32(ei);
    __syncthreads();
    int is32 = s32s;
    int lane = threadIdx.x & 31;
    int gw = (blockIdx.x * blockDim.x + threadIdx.x) >> 5;
    int base = gw * 64;
    if (base >= E) return;
    int cnt = min(64, E - base);

    int pe_l[2], d_l[2];
    #pragma unroll
    for (int j = 0; j < 2; j++) {
        int idx = base + j * 32 + lane;
        if (idx < E) {
            pe_l[j] = g_perm[idx];
            d_l[j] = dst_at(ei, pe_l[j], is32);
        } else { pe_l[j] = 0; d_l[j] = -1; }
    }

    const float4* keL = (const float4*)ke + lane;
    const float4* veL = (const float4*)ve + lane;

    int i1 = (1 < cnt) ? 1 : 0;
    int pa = __shfl_sync(0xffffffffu, pe_l[0], 0);
    int pb = __shfl_sync(0xffffffffu, pe_l[i1 >> 5], i1 & 31);
    float4 k0 = __ldg(keL + (size_t)pa * 32), v0 = __ldg(veL + (size_t)pa * 32);
    float4 k1 = __ldg(keL + (size_t)pb * 32), v1 = __ldg(veL + (size_t)pb * 32);

    float4 wt0, wt1, wt2, wt3, cv;    // wt for heads 0..3 at lane's 4 elems
    wt0 = wt1 = wt2 = wt3 = cv = make_float4(0.f, 0.f, 0.f, 0.f);
    float4 a0 = make_float4(0.f, 0.f, 0.f, 0.f), a1 = a0, a2 = a0, a3 = a0, aden = a0;
    int prevd = -1;

    for (int i = 0; i < cnt; i++) {
        int inx = (i + 2 < cnt) ? i + 2 : i;
        int pn = __shfl_sync(0xffffffffu, pe_l[inx >> 5], inx & 31);
        float4 k2 = __ldg(keL + (size_t)pn * 32);
        float4 v2 = __ldg(veL + (size_t)pn * 32);

        int d = __shfl_sync(0xffffffffu, d_l[i >> 5], i & 31);
        if (d != prevd) {
            if (prevd >= 0) {
                float* S = g_S + (size_t)prevd * 512 + lane * 4;
                atomicAdd(S + 0,   a0.x); atomicAdd(S + 1,   a0.y); atomicAdd(S + 2,   a0.z); atomicAdd(S + 3,   a0.w);
                atomicAdd(S + 128, a1.x); atomicAdd(S + 129, a1.y); atomicAdd(S + 130, a1.z); atomicAdd(S + 131, a1.w);
                atomicAdd(S + 256, a2.x); atomicAdd(S + 257, a2.y); atomicAdd(S + 258, a2.z); atomicAdd(S + 259, a2.w);
                atomicAdd(S + 384, a3.x); atomicAdd(S + 385, a3.y); atomicAdd(S + 386, a3.z); atomicAdd(S + 387, a3.w);
                if (lane == 0) {
                    atomicAdd(&g_den[prevd * 4 + 0], aden.x);
                    atomicAdd(&g_den[prevd * 4 + 1], aden.y);
                    atomicAdd(&g_den[prevd * 4 + 2], aden.z);
                    atomicAdd(&g_den[prevd * 4 + 3], aden.w);
                }
                a0 = a1 = a2 = a3 = aden = make_float4(0.f, 0.f, 0.f, 0.f);
            }
            const float4* bw = (const float4*)(g_wt + (size_t)d * 512) + lane;
            wt0 = __ldg(bw); wt1 = __ldg(bw + 32); wt2 = __ldg(bw + 64); wt3 = __ldg(bw + 96);
            cv = __ldg((const float4*)(g_c + d * 4));
            prevd = d;
        }

        // per-lane partial dots for the 4 heads
        float q0 = k0.x * wt0.x + k0.y * wt0.y + k0.z * wt0.z + k0.w * wt0.w;
        float q1 = k0.x * wt1.x + k0.y * wt1.y + k0.z * wt1.z + k0.w * wt1.w;
        float q2 = k0.x * wt2.x + k0.y * wt2.y + k0.z * wt2.z + k0.w * wt2.w;
        float q3 = k0.x * wt3.x + k0.y * wt3.y + k0.z * wt3.z + k0.w * wt3.w;

        // value-folding butterfly: 6 shfl total; lane ends with head (lane&3) sum
        float ta = (lane & 1) ? q0 : q1;
        float ra = __shfl_xor_sync(0xffffffffu, ta, 1);
        float fa = ((lane & 1) ? q1 : q0) + ra;          // head (lane&1) over pair
        float tb = (lane & 1) ? q2 : q3;
        float rb = __shfl_xor_sync(0xffffffffu, tb, 1);
        float fb = ((lane & 1) ? q3 : q2) + rb;          // head 2+(lane&1) over pair
        float tc = (lane & 2) ? fa : fb;
        float rc = __shfl_xor_sync(0xffffffffu, tc, 2);
        float fc = ((lane & 2) ? fb : fa) + rc;          // head (lane&3) over quad
        fc += __shfl_xor_sync(0xffffffffu, fc, 4);
        fc += __shfl_xor_sync(0xffffffffu, fc, 8);
        fc += __shfl_xor_sync(0xffffffffu, fc, 16);      // full 32-lane sum

        int hs = lane & 3;
        float cgh = (hs == 0) ? cv.x : (hs == 1) ? cv.y : (hs == 2) ? cv.z : cv.w;
        float e = __expf(fc + cgh);

        // re-gather all 4 head e's into every lane: 3 shfl + selects
        float s1 = __shfl_xor_sync(0xffffffffu, e, 1);
        float e_even = (lane & 1) ? s1 : e;              // head (lane&2)
        float e_odd  = (lane & 1) ? e : s1;              // head (lane&2)+1
        float s2e = __shfl_xor_sync(0xffffffffu, e_even, 2);
        float s2o = __shfl_xor_sync(0xffffffffu, e_odd, 2);
        float e0 = (lane & 2) ? s2e : e_even;
        float e2 = (lane & 2) ? e_even : s2e;
        float e1 = (lane & 2) ? s2o : e_odd;
        float e3 = (lane & 2) ? e_odd : s2o;

        a0.x += e0 * v0.x; a0.y += e0 * v0.y; a0.z += e0 * v0.z; a0.w += e0 * v0.w;
        a1.x += e1 * v0.x; a1.y += e1 * v0.y; a1.z += e1 * v0.z; a1.w += e1 * v0.w;
        a2.x += e2 * v0.x; a2.y += e2 * v0.y; a2.z += e2 * v0.z; a2.w += e2 * v0.w;
        a3.x += e3 * v0.x; a3.y += e3 * v0.y; a3.z += e3 * v0.z; a3.w += e3 * v0.w;
        aden.x += e0; aden.y += e1; aden.z += e2; aden.w += e3;

        k0 = k1; v0 = v1; k1 = k2; v1 = v2;
    }
    // final flush
    {
        float* S = g_S + (size_t)prevd * 512 + lane * 4;
        atomicAdd(S + 0,   a0.x); atomicAdd(S + 1,   a0.y); atomicAdd(S + 2,   a0.z); atomicAdd(S + 3,   a0.w);
        atomicAdd(S + 128, a1.x); atomicAdd(S + 129, a1.y); atomicAdd(S + 130, a1.z); atomicAdd(S + 131, a1.w);
        atomicAdd(S + 256, a2.x); atomicAdd(S + 257, a2.y); atomicAdd(S + 258, a2.z); atomicAdd(S + 259, a2.w);
        atomicAdd(S + 384, a3.x); atomicAdd(S + 385, a3.y); atomicAdd(S + 386, a3.z); atomicAdd(S + 387, a3.w);
        if (lane == 0) {
            atomicAdd(&g_den[prevd * 4 + 0], aden.x);
            atomicAdd(&g_den[prevd * 4 + 1], aden.y);
            atomicAdd(&g_den[prevd * 4 + 2], aden.z);
            atomicAdd(&g_den[prevd * 4 + 3], aden.w);
        }
    }
}

// ---------------- launch 4: agg = (S @ Wv)/den + bv (+ self-clean; smem = Ss only) ----------------
__global__ __launch_bounds__(256) void k_vproj(const float* __restrict__ Wv,
                                               const float* __restrict__ bv, int n) {
    extern __shared__ float sq[];
    float* Ss = sq;               // [32][4][136]
    int tid = threadIdx.x;
    int row0 = blockIdx.x * 32;
    for (int i = tid; i < 32 * 512; i += 256) {
        int nl = i >> 9, rest = i & 511;
        int h = rest >> 7, d = rest & 127;
        int gr = row0 + nl;
        float v = 0.f;
        if (gr < n) {
            size_t idx = (size_t)gr * 512 + rest;
            v = g_S[idx];
            g_S[idx] = 0.f;
        }
        Ss[nl * 544 + h * 136 + d] = v;
    }
    __syncthreads();
    int cg = (tid & 31) * 4, rg = (tid >> 5) * 4;
    int h = cg >> 5;
    float acc[4][4] = {};
    #pragma unroll 8
    for (int d = 0; d < DIM; d++) {
        float4 wv = __ldg((const float4*)&Wv[d * DIM + cg]);
        float a0 = Ss[(rg + 0) * 544 + h * 136 + d];
        float a1 = Ss[(rg + 1) * 544 + h * 136 + d];
        float a2 = Ss[(rg + 2) * 544 + h * 136 + d];
        float a3 = Ss[(rg + 3) * 544 + h * 136 + d];
        acc[0][0] += a0 * wv.x; acc[0][1] += a0 * wv.y; acc[0][2] += a0 * wv.z; acc[0][3] += a0 * wv.w;
        acc[1][0] += a1 * wv.x; acc[1][1] += a1 * wv.y; acc[1][2] += a1 * wv.z; acc[1][3] += a1 * wv.w;
        acc[2][0] += a2 * wv.x; acc[2][1] += a2 * wv.y; acc[2][2] += a2 * wv.z; acc[2][3] += a2 * wv.w;
        acc[3][0] += a3 * wv.x; acc[3][1] += a3 * wv.y; acc[3][2] += a3 * wv.z; acc[3][3] += a3 * wv.w;
    }
    float4 bb = __ldg((const float4*)&bv[cg]);
    #pragma unroll
    for (int rr = 0; rr < 4; rr++) {
        int gr = row0 + rg + rr;
        if (gr < n) {
            float den = g_den[gr * HEADS + h];
            float4 o;
            if (den > 0.f) {
                float inv = 1.f / den;
                o = make_float4(acc[rr][0] * inv + bb.x, acc[rr][1] * inv + bb.y,
                                acc[rr][2] * inv + bb.z, acc[rr][3] * inv + bb.w);
            } else {
                o = make_float4(0.f, 0.f, 0.f, 0.f);
            }
            *(float4*)&g_agg[gr * DIM + cg] = o;
        }
    }
    __syncthreads();
    for (int i = tid; i < 32 * HEADS; i += 256) {
        int gr = row0 + (i >> 2);
        if (gr < n) g_den[gr * HEADS + (i & 3)] = 0.f;
    }
}

// ---------------- launch 5: out = agg @ Wo + bo (smem = As only) ----------------
__global__ __launch_bounds__(256) void k_out(const float* __restrict__ W,
                                             const float* __restrict__ b,
                                             float* __restrict__ Y, int n) {
    extern __shared__ float so[];
    float* As = so;               // [32][132]
    int tid = threadIdx.x;
    int row0 = blockIdx.x * 32;
    for (int i = tid; i < 32 * DIM; i += 256) {
        int r = i >> 7, c = i & 127;
        int gr = row0 + r;
        As[r * 132 + c] = (gr < n) ? g_agg[gr * DIM + c] : 0.f;
    }
    __syncthreads();
    int cg = (tid & 31) * 4, rg = (tid >> 5) * 4;
    float acc[4][4] = {};
    #pragma unroll 8
    for (int d = 0; d < DIM; d++) {
        float4 w = __ldg((const float4*)&W[d * DIM + cg]);
        float a0 = As[(rg + 0) * 132 + d];
        float a1 = As[(rg + 1) * 132 + d];
        float a2 = As[(rg + 2) * 132 + d];
        float a3 = As[(rg + 3) * 132 + d];
        acc[0][0] += a0 * w.x; acc[0][1] += a0 * w.y; acc[0][2] += a0 * w.z; acc[0][3] += a0 * w.w;
        acc[1][0] += a1 * w.x; acc[1][1] += a1 * w.y; acc[1][2] += a1 * w.z; acc[1][3] += a1 * w.w;
        acc[2][0] += a2 * w.x; acc[2][1] += a2 * w.y; acc[2][2] += a2 * w.z; acc[2][3] += a2 * w.w;
        acc[3][0] += a3 * w.x; acc[3][1] += a3 * w.y; acc[3][2] += a3 * w.z; acc[3][3] += a3 * w.w;
    }
    float4 bb = __ldg((const float4*)&b[cg]);
    #pragma unroll
    for (int rr = 0; rr < 4; rr++) {
        int gr = row0 + rg + rr;
        if (gr < n) {
            float4 o = make_float4(acc[rr][0] + bb.x, acc[rr][1] + bb.y,
                                   acc[rr][2] + bb.z, acc[rr][3] + bb.w);
            *(float4*)&Y[gr * DIM + cg] = o;
        }
    }
}

extern "C" void kernel_launch(void* const* d_in, const int* in_sizes, int n_in,
                              void* d_out, int out_size) {
    const float* q_nodes = (const float*)d_in[0];
    const float* k_edges = (const float*)d_in[1];
    const float* v_edges = (const float*)d_in[2];
    const float* Wq = (const float*)d_in[3];
    const float* bq = (const float*)d_in[4];
    const float* Wk = (const float*)d_in[5];
    const float* bk = (const float*)d_in[6];
    const float* Wv = (const float*)d_in[7];
    const float* bv = (const float*)d_in[8];
    const float* Wo = (const float*)d_in[9];
    const float* bo = (const float*)d_in[10];
    const void*  ei = (const void*)d_in[11];

    int N = in_sizes[0] / DIM;
    int E = in_sizes[1] / DIM;

    const int smem_ws  = 64 * 132 * (int)sizeof(float);   // 33792
    const int smem_vp  = 32 * 544 * (int)sizeof(float);   // 69632
    const int smem_out = 32 * 132 * (int)sizeof(float);   // 16896
    cudaFuncSetAttribute(k_wt_scatter, cudaFuncAttributeMaxDynamicSharedMemorySize, smem_ws);
    cudaFuncSetAttribute(k_vproj, cudaFuncAttributeMaxDynamicSharedMemorySize, smem_vp);
    cudaFuncSetAttribute(k_out, cudaFuncAttributeMaxDynamicSharedMemorySize, smem_out);

    int nblk = (N + 31) / 32;
    int histBlocks = (E + 255) / 256;
    int wtBlocks = ((N + 63) / 64) * 4;
    int ewarps = (E + 63) / 64;
    int eblocks = (ewarps + 7) / 8;

    k_hist_prep<<<32 + histBlocks, 256>>>(Wq, bq, Wk, bk, ei, E);                        // 0
    k_scan<<<1, 1024>>>(N);                                                              // 1
    k_wt_scatter<<<wtBlocks + histBlocks, 256, smem_ws>>>(q_nodes, ei, N, E, wtBlocks);  // 2
    k_edge<<<eblocks, 256>>>(k_edges, v_edges, ei, E);                                   // 3 (profiled)
    k_vproj<<<nblk, 256, smem_vp>>>(Wv, bv, N);                                          // 4
    k_out<<<nblk, 256, smem_out>>>(Wo, bo, (float*)d_out, N);                            // 5
}